// round 4
// baseline (speedup 1.0000x reference)
#include <cuda_runtime.h>
#include <cuda_bf16.h>

// Seq2SeqLoss: label-smoothed weighted cross-entropy, mean over masked rows.
// Harness canonicalizes dtypes to {f32, i32, bf16}:
//   [0] outputs  f32 [B*S*C] = 131072000
//   [1] gold     i32 [B*S]   = 4096   (int64 -> int32)
//   [2] mask     i32 [B*S]   = 4096   (bool  -> int32)
//   [3] weight   f32 [C]     = 32000
// output: f32 scalar

#define SMOOTHING 0.1f
#define EPSILON   1e-8f
#define MAX_ROWS  8192

__device__ float g_sum_exp[MAX_ROWS];
__device__ float g_dot[MAX_ROWS];

// All-FMA exp (no MUFU): exp(x) = 2^(x*log2e), magic-number round,
// degree-5 poly for 2^f on [-0.5,0.5] (rel err ~2.4e-6), exponent splice.
__device__ __forceinline__ float fexp(float x) {
    float t = x * 1.4426950408889634f;
    t = fminf(fmaxf(t, -126.0f), 126.0f);
    float r = t + 12582912.0f;                 // round-to-nearest-int via RN add
    int   eb = __float_as_int(r) << 23;        // n<<23 (two's-complement wrap ok)
    float nf = r - 12582912.0f;
    float f  = t - nf;                         // f in [-0.5, 0.5]
    float p  = 1.3333558146428443e-3f;
    p = fmaf(p, f, 9.6181291076284772e-3f);
    p = fmaf(p, f, 5.5504108664821580e-2f);
    p = fmaf(p, f, 2.4022650695910072e-1f);
    p = fmaf(p, f, 6.9314718055994531e-1f);
    p = fmaf(p, f, 1.0f);
    return __int_as_float(__float_as_int(p) + eb);
}

__device__ __forceinline__ float warp_sum(float v) {
    #pragma unroll
    for (int o = 16; o > 0; o >>= 1) v += __shfl_xor_sync(0xffffffffu, v, o);
    return v;
}

// Kernel 1: one CTA per row. Stream logits once (__ldcs, evict-first),
// weight via __ldg (L2-resident). Produce sum_exp[row] and dot[row].
__global__ __launch_bounds__(256) void row_reduce_kernel(
    const float* __restrict__ logits,
    const float* __restrict__ weight,
    int C4)
{
    const int row = blockIdx.x;
    const float4* lp = reinterpret_cast<const float4*>(logits) + (size_t)row * C4;
    const float4* wp = reinterpret_cast<const float4*>(weight);

    float s = 0.0f, d = 0.0f;
    #pragma unroll 4
    for (int i = threadIdx.x; i < C4; i += 256) {
        float4 x = __ldcs(lp + i);
        float4 w = __ldg(wp + i);
        d = fmaf(x.x, w.x, d);
        d = fmaf(x.y, w.y, d);
        d = fmaf(x.z, w.z, d);
        d = fmaf(x.w, w.w, d);
        s += fexp(x.x);
        s += fexp(x.y);
        s += fexp(x.z);
        s += fexp(x.w);
    }

    __shared__ float sh_s[8], sh_d[8];
    s = warp_sum(s);
    d = warp_sum(d);
    const int wid = threadIdx.x >> 5;
    const int lid = threadIdx.x & 31;
    if (lid == 0) { sh_s[wid] = s; sh_d[wid] = d; }
    __syncthreads();
    if (wid == 0) {
        float ss = (lid < 8) ? sh_s[lid] : 0.0f;
        float dd = (lid < 8) ? sh_d[lid] : 0.0f;
        ss = warp_sum(ss);
        dd = warp_sum(dd);
        if (lid == 0) {
            g_sum_exp[row] = ss;
            g_dot[row]     = dd;
        }
    }
}

// Kernel 2: one CTA. sumW over weight, then per-row gold gather + combine,
// final masked mean.
__global__ __launch_bounds__(1024) void finalize_kernel(
    const float* __restrict__ logits,
    const int* __restrict__ gold,
    const int* __restrict__ mask,
    const float* __restrict__ weight,
    float* __restrict__ out,
    int N, int C)
{
    const int tid = threadIdx.x;
    __shared__ float sh[32];
    __shared__ float sh_m[32];
    __shared__ float sh_sumw;

    // sumW
    float w = 0.0f;
    for (int i = tid; i < C; i += 1024) w += weight[i];
    w = warp_sum(w);
    if ((tid & 31) == 0) sh[tid >> 5] = w;
    __syncthreads();
    if (tid < 32) {
        float v = sh[tid];                       // 1024/32 = 32 warps exactly
        v = warp_sum(v);
        if (tid == 0) sh_sumw = v;
    }
    __syncthreads();
    const float sumW = sh_sumw;

    const float uniform = SMOOTHING / (float)(C - 1);
    const float conf    = 1.0f - SMOOTHING;
    const float cmu     = conf - uniform;

    float loss_sum = 0.0f, mask_sum = 0.0f;
    for (int r = tid; r < N; r += 1024) {
        int   g    = gold[r];
        float se   = g_sum_exp[r];
        float lse  = logf(se);
        float xg   = __ldg(logits + (size_t)r * C + (size_t)g);
        float wg   = __ldg(weight + g);
        float m    = (mask[r] != 0) ? 1.0f : 0.0f;
        float loss = uniform * fmaf(sumW, lse, -g_dot[r]) + cmu * wg * (lse - xg);
        loss_sum += loss * m;
        mask_sum += m;
    }
    __syncthreads();

    loss_sum = warp_sum(loss_sum);
    mask_sum = warp_sum(mask_sum);
    if ((tid & 31) == 0) { sh[tid >> 5] = loss_sum; sh_m[tid >> 5] = mask_sum; }
    __syncthreads();
    if (tid < 32) {
        float ls = sh[tid];
        float ms = sh_m[tid];
        ls = warp_sum(ls);
        ms = warp_sum(ms);
        if (tid == 0) out[0] = ls / (ms + EPSILON);
    }
}

extern "C" void kernel_launch(void* const* d_in, const int* in_sizes, int n_in,
                              void* d_out, int out_size)
{
    const float* logits = (const float*)d_in[0];
    const int*   gold   = (const int*)d_in[1];
    const int*   mask   = (const int*)d_in[2];
    const float* weight = (const float*)d_in[3];
    float*       out    = (float*)d_out;

    const int N = in_sizes[1];     // B*S rows
    const int C = in_sizes[3];     // classes
    const int C4 = C / 4;

    row_reduce_kernel<<<N, 256>>>(logits, weight, C4);
    finalize_kernel<<<1, 1024>>>(logits, gold, mask, weight, out, N, C);
}